// round 7
// baseline (speedup 1.0000x reference)
#include <cuda_runtime.h>
#include <cstdint>

// Problem constants
#define BATCH   32768
#define TSTEPS  30
#define HID     384
#define KTOT    392     // 8 rowvec + 384 hidden
#define NKB     49      // K blocks of 8
#define NMAIN   144     // fragments per kb in main B (24 ub * 6)
#define MROWS   64      // batch rows per CTA
#define NTH     512     // 16 warps, each owns 8-col sub-blocks (usb)
#define LDH     392     // packed row stride in floats (392 % 32 == 8 -> LDS.64 conflict-free)
#define LDH2    196     // row stride in float2
#define ASZ     (MROWS*LDH)

// -------- static device scratch --------
__device__ float2 g_B2[NKB * NMAIN * 32];   // main GEMM B (r,z,n_h), fragment order
__device__ float2 g_Bni[48 * 32];           // n_i B: kb=0 only, 48 usb
__device__ float2 g_Wd1f2[48 * 8 * 32];     // decode B, fragment order

__device__ __forceinline__ float to_tf32(float x) {
    unsigned u; asm("cvt.rna.tf32.f32 %0, %1;" : "=r"(u) : "f"(x));
    return __uint_as_float(u);
}
__device__ __forceinline__ float sigf(float x) { return 1.0f / (1.0f + __expf(-x)); }
__device__ __forceinline__ float tanhf_fast(float x) {
    return 2.0f / (1.0f + __expf(-2.0f * x)) - 1.0f;
}
// packed float offset of logical column c within a row
__device__ __forceinline__ int pcol(int c) {
    return (c & ~7) + ((c & 3) << 1) + ((c >> 2) & 1);
}

__device__ __forceinline__ void mma_tf32r(float* c, const unsigned* a, unsigned b0, unsigned b1) {
    asm volatile(
        "mma.sync.aligned.m16n8k8.row.col.f32.tf32.tf32.f32 "
        "{%0,%1,%2,%3}, {%4,%5,%6,%7}, {%8,%9}, {%0,%1,%2,%3};\n"
        : "+f"(c[0]), "+f"(c[1]), "+f"(c[2]), "+f"(c[3])
        : "r"(a[0]), "r"(a[1]), "r"(a[2]), "r"(a[3]), "r"(b0), "r"(b1));
}

// -------- prep helpers (layouts identical to rounds 4-6) --------
__device__ float bval_main(int k, int ub, int colub,
                           const float* Wih, const float* bih,
                           const float* Whh, const float* bhh,
                           const float* Wp, const float* bp,
                           const float* Ws, const float* bs) {
    int gate = colub >> 4;          // 0=r,1=z,2=n_h
    int u = ub * 16 + (colub & 15);
    if (k >= 8) {
        int kk = k - 8;
        int grow = (gate == 2 ? 768 : gate * 384) + u;
        return Whh[grow * HID + kk];
    }
    if (gate == 2) return (k == 0) ? bhh[768 + u] : 0.0f;   // n_h: bias only
    int grow = gate * 384 + u;
    const float* wr = Wih + grow * 128;
    float s = 0.0f;
    if (k == 0) {
        s = bih[grow] + bhh[grow];
        for (int m = 0; m < 128; m++) s += bs[m] * wr[m];
    } else if (k == 1) {
        for (int m = 0; m < 128; m++) s += bp[m] * wr[m];
    } else if (k < 5) {
        int d = k - 2;
        for (int m = 0; m < 128; m++) s += Ws[m * 3 + d] * wr[m];
    } else {
        int d = k - 5;
        for (int m = 0; m < 128; m++) s += Wp[m * 3 + d] * wr[m];
    }
    return s;
}

__device__ float bval_ni(int k, int u,
                         const float* Wih, const float* bih,
                         const float* Wp, const float* bp,
                         const float* Ws, const float* bs) {
    int grow = 768 + u;
    const float* wr = Wih + grow * 128;
    float s = 0.0f;
    if (k == 0) {
        s = bih[grow];
        for (int m = 0; m < 128; m++) s += bs[m] * wr[m];
    } else if (k == 1) {
        for (int m = 0; m < 128; m++) s += bp[m] * wr[m];
    } else if (k < 5) {
        int d = k - 2;
        for (int m = 0; m < 128; m++) s += Ws[m * 3 + d] * wr[m];
    } else {
        int d = k - 5;
        for (int m = 0; m < 128; m++) s += Wp[m * 3 + d] * wr[m];
    }
    return s;
}

__global__ void prep_kernel(const float* __restrict__ W_ih, const float* __restrict__ b_ih,
                            const float* __restrict__ W_hh, const float* __restrict__ b_hh,
                            const float* __restrict__ Wp,  const float* __restrict__ bp,
                            const float* __restrict__ Ws,  const float* __restrict__ bs,
                            const float* __restrict__ Wd1) {
    int gid = blockIdx.x * blockDim.x + threadIdx.x;
    int nMain = NKB * NMAIN;
    int total = (nMain + 48 + 48 * 8) * 32;
    for (int w = gid; w < total; w += gridDim.x * blockDim.x) {
        int fid = w >> 5, lane = w & 31;
        int tig = lane & 3, g = lane >> 2;
        if (fid < nMain) {
            int kb = fid / NMAIN, rem = fid - kb * NMAIN;
            int ub = rem / 6, n8l = rem - ub * 6;
            int colub = n8l * 8 + g;
            float b0 = bval_main(kb * 8 + tig,     ub, colub, W_ih, b_ih, W_hh, b_hh, Wp, bp, Ws, bs);
            float b1 = bval_main(kb * 8 + tig + 4, ub, colub, W_ih, b_ih, W_hh, b_hh, Wp, bp, Ws, bs);
            g_B2[fid * 32 + lane] = make_float2(to_tf32(b0), to_tf32(b1));
        } else if (fid < nMain + 48) {
            int f = fid - nMain;            // usb = ub*2 + uh
            int ub = f >> 1, n8l = f & 1;
            int u = ub * 16 + n8l * 8 + g;
            float b0 = bval_ni(tig,     u, W_ih, b_ih, Wp, bp, Ws, bs);
            float b1 = bval_ni(tig + 4, u, W_ih, b_ih, Wp, bp, Ws, bs);
            g_Bni[f * 32 + lane] = make_float2(to_tf32(b0), to_tf32(b1));
        } else {
            int f = fid - nMain - 48;       // 48 kb * 8 n8
            int kb = f >> 3, n8 = f & 7;
            int n = n8 * 8 + g;
            int k = kb * 8 + tig;
            float b0 = Wd1[n * HID + k];
            float b1 = Wd1[n * HID + k + 4];
            g_Wd1f2[f * 32 + lane] = make_float2(to_tf32(b0), to_tf32(b1));
        }
    }
}

// -------- main fused GRU rollout --------
__global__ __launch_bounds__(NTH, 1)
void gru_kernel(const float* __restrict__ init_hidden,
                const float* __restrict__ plan,
                const float* __restrict__ gate,
                const float* __restrict__ init_state,
                const float* __restrict__ bd1,
                const float* __restrict__ Wd2,
                const float* __restrict__ bd2,
                float* __restrict__ out) {
    extern __shared__ float sm[];
    float* sA0  = sm;                  // [MROWS][LDH] packed, ping
    float* sA1  = sA0 + ASZ;           // pong
    float* sDec = sA1 + ASZ;           // [64][68]
    float* sbd1 = sDec + 64 * 68;      // [64]
    float* sWd2 = sbd1 + 64;           // [3*64]
    float* sbd2 = sWd2 + 192;          // [4]

    const int tid  = threadIdx.x;
    const int warp = tid >> 5;
    const int lane = tid & 31;
    const int g8   = lane >> 2;
    const int tig  = lane & 3;
    const int row0 = blockIdx.x * MROWS;
    const int pbase = (tig < 2) ? 4 * tig : 4 * tig - 7;   // packed epilogue offset

    // per-thread state lane (valid for tid < 192)
    const int pr = tid / 3;
    const int pc = tid - pr * 3;
    float st = 0.0f, gx = 0.0f;
    int pc2 = 0, pc5 = 0;

    // ---- init ----
    for (int i = tid; i < MROWS * HID; i += NTH) {
        int r = i / HID, u = i - r * HID;
        sA0[r * LDH + pcol(8 + u)] = to_tf32(init_hidden[(size_t)row0 * HID + i]);
    }
    if (tid < 192) {
        st = init_state[(size_t)row0 * 3 + tid];
        gx = gate[row0 + pr];
        pc2 = pcol(2 + pc);
        pc5 = pcol(5 + pc);
        sA0[pr * LDH + pc2] = to_tf32(st);
        float p0 = plan[((size_t)(row0 + pr) * TSTEPS + 0) * 3 + pc];
        sA0[pr * LDH + pc5] = to_tf32(gx * p0);
        if (pc == 0) {
            sA0[pr * LDH + 0] = 1.0f;         sA1[pr * LDH + 0] = 1.0f;
            sA0[pr * LDH + 2] = to_tf32(gx);  sA1[pr * LDH + 2] = to_tf32(gx);  // pcol(1)=2
        }
        sWd2[tid] = Wd2[tid];
    }
    if (tid < 64) sbd1[tid] = bd1[tid];
    if (tid < 3)  sbd2[tid] = bd2[tid];
    __syncthreads();

    for (int t = 0; t < TSTEPS; t++) {
        float* Acur = (t & 1) ? sA1 : sA0;
        float* Anxt = (t & 1) ? sA0 : sA1;
        const float2* A2 = (const float2*)Acur;

        // prefetch plan(t+1), hidden behind the GEMM
        float pl = 0.0f;
        if (t < TSTEPS - 1 && tid < 192)
            pl = plan[((size_t)(row0 + pr) * TSTEPS + t + 1) * 3 + pc];

        // ---- phase 1: GEMM (64 x 1152 dense + n_i micro) + gate math ----
        for (int task = 0; task < 3; task++) {
            const int usb = warp + task * 16;   // 8-col sub-block 0..47
            const int ub  = usb >> 1;
            const int uh  = usb & 1;

            float acc[48];                      // [mf=4][gate=3] x 4
            float accN[16];                     // [mf=4] x 4 (n_i)
            #pragma unroll
            for (int i = 0; i < 48; i++) acc[i] = 0.0f;
            #pragma unroll
            for (int i = 0; i < 16; i++) accN[i] = 0.0f;

            const float2* Bbase = g_B2 + (size_t)(ub * 6 + uh) * 32 + lane;
            float2 bb[4][3];                    // 4-stage B pipeline
            #pragma unroll
            for (int s = 0; s < 3; s++)
                #pragma unroll
                for (int gi = 0; gi < 3; gi++)
                    bb[s][gi] = Bbase[(size_t)s * (NMAIN * 32) + gi * 64];
            float2 bni = g_Bni[usb * 32 + lane];

            #pragma unroll 4
            for (int kb = 0; kb < NKB; kb++) {
                const int cur = kb & 3;
                if (kb + 3 < NKB) {
                    const float2* Bn = Bbase + (size_t)(kb + 3) * (NMAIN * 32);
                    #pragma unroll
                    for (int gi = 0; gi < 3; gi++)
                        bb[(kb + 3) & 3][gi] = Bn[gi * 64];
                }
                // A fragments: packed LDS.64, conflict-free
                unsigned a[16];
                #pragma unroll
                for (int mf = 0; mf < 4; mf++) {
                    int r0 = mf * 16 + g8;
                    float2 lo = A2[r0 * LDH2 + kb * 4 + tig];
                    float2 hi = A2[(r0 + 8) * LDH2 + kb * 4 + tig];
                    a[mf * 4 + 0] = __float_as_uint(lo.x);
                    a[mf * 4 + 1] = __float_as_uint(hi.x);
                    a[mf * 4 + 2] = __float_as_uint(lo.y);
                    a[mf * 4 + 3] = __float_as_uint(hi.y);
                }
                if (kb == 0) {   // n_i: rowvec-only contribution
                    unsigned nx = __float_as_uint(bni.x), ny = __float_as_uint(bni.y);
                    #pragma unroll
                    for (int mf = 0; mf < 4; mf++)
                        mma_tf32r(&accN[mf * 4], &a[mf * 4], nx, ny);
                }
                #pragma unroll
                for (int gi = 0; gi < 3; gi++) {
                    unsigned b0 = __float_as_uint(bb[cur][gi].x);
                    unsigned b1 = __float_as_uint(bb[cur][gi].y);
                    #pragma unroll
                    for (int mf = 0; mf < 4; mf++)
                        mma_tf32r(&acc[(mf * 3 + gi) * 4], &a[mf * 4], b0, b1);
                }
            }

            // gate math on fragments
            #pragma unroll
            for (int mf = 0; mf < 4; mf++)
            #pragma unroll
            for (int e = 0; e < 4; e++) {
                int row = mf * 16 + g8 + ((e >> 1) << 3);
                int off = row * LDH + 8 + usb * 8 + pbase + ((e & 1) << 1);
                float aR  = acc[(mf * 3 + 0) * 4 + e];
                float aZ  = acc[(mf * 3 + 1) * 4 + e];
                float aNh = acc[(mf * 3 + 2) * 4 + e];
                float aNi = accN[mf * 4 + e];
                float rg = sigf(aR);
                float zg = sigf(aZ);
                float n  = tanhf_fast(aNi + rg * aNh);
                float hold = Acur[off];
                float hnew = (1.0f - zg) * n + zg * hold;
                Anxt[off] = to_tf32(hnew);
            }
        }
        __syncthreads();

        // ---- phase 2: decode layer1 (64x64, K=384) ----
        {
            const int c8 = warp & 7;        // column block (8 cols)
            const int mh = warp >> 3;       // M half
            const float2* A2n = (const float2*)Anxt;
            float dacc[8];
            #pragma unroll
            for (int i = 0; i < 8; i++) dacc[i] = 0.0f;

            float2 bv = g_Wd1f2[c8 * 32 + lane];
            #pragma unroll 2
            for (int kd = 0; kd < 48; kd++) {
                float2 bcur = bv;
                if (kd < 47) bv = g_Wd1f2[((kd + 1) * 8 + c8) * 32 + lane];
                unsigned a[8];
                #pragma unroll
                for (int mf = 0; mf < 2; mf++) {
                    int r0 = mh * 32 + mf * 16 + g8;
                    float2 lo = A2n[r0 * LDH2 + 4 + kd * 4 + tig];
                    float2 hi = A2n[(r0 + 8) * LDH2 + 4 + kd * 4 + tig];
                    a[mf * 4 + 0] = __float_as_uint(lo.x);
                    a[mf * 4 + 1] = __float_as_uint(hi.x);
                    a[mf * 4 + 2] = __float_as_uint(lo.y);
                    a[mf * 4 + 3] = __float_as_uint(hi.y);
                }
                unsigned b0 = __float_as_uint(bcur.x), b1 = __float_as_uint(bcur.y);
                #pragma unroll
                for (int mf = 0; mf < 2; mf++)
                    mma_tf32r(&dacc[mf * 4], &a[mf * 4], b0, b1);
            }
            #pragma unroll
            for (int mf = 0; mf < 2; mf++)
            #pragma unroll
            for (int e = 0; e < 4; e++) {
                int row = mh * 32 + mf * 16 + g8 + ((e >> 1) << 3);
                int col = c8 * 8 + tig * 2 + (e & 1);
                float v = dacc[mf * 4 + e] + sbd1[col];
                v = v > 0.0f ? v : (__expf(v) - 1.0f);   // ELU
                sDec[row * 68 + col] = v;
            }
        }
        __syncthreads();

        // ---- phase 3: decode layer2 + state update + output + next rowvec ----
        if (tid < 192) {
            float acc = sbd2[pc];
            const float* w2 = sWd2 + pc * 64;
            const float* dp = sDec + pr * 68;
            #pragma unroll 16
            for (int k = 0; k < 64; k++) acc += dp[k] * w2[k];
            st += acc;
            out[((size_t)(row0 + pr) * TSTEPS + t) * 3 + pc] = st;
            if (t < TSTEPS - 1) {
                Anxt[pr * LDH + pc2] = to_tf32(st);
                Anxt[pr * LDH + pc5] = to_tf32(gx * pl);
            }
        }
        __syncthreads();
    }
}

// -------- launch --------
extern "C" void kernel_launch(void* const* d_in, const int* in_sizes, int n_in,
                              void* d_out, int out_size) {
    const float* init_hidden = (const float*)d_in[0];
    const float* plan        = (const float*)d_in[1];
    const float* gatep       = (const float*)d_in[2];
    const float* init_state  = (const float*)d_in[3];
    const float* Wp   = (const float*)d_in[4];
    const float* bp   = (const float*)d_in[5];
    const float* Ws   = (const float*)d_in[6];
    const float* bs   = (const float*)d_in[7];
    const float* W_ih = (const float*)d_in[8];
    const float* b_ih = (const float*)d_in[9];
    const float* W_hh = (const float*)d_in[10];
    const float* b_hh = (const float*)d_in[11];
    const float* Wd1  = (const float*)d_in[12];
    const float* bd1  = (const float*)d_in[13];
    const float* Wd2  = (const float*)d_in[14];
    const float* bd2  = (const float*)d_in[15];
    float* out = (float*)d_out;

    prep_kernel<<<640, 256>>>(W_ih, b_ih, W_hh, b_hh, Wp, bp, Ws, bs, Wd1);

    const size_t smem_floats = 2 * (size_t)ASZ + 64 * 68 + 64 + 192 + 4;
    const size_t smem_bytes = smem_floats * sizeof(float);
    cudaFuncSetAttribute(gru_kernel, cudaFuncAttributeMaxDynamicSharedMemorySize,
                         (int)smem_bytes);

    gru_kernel<<<BATCH / MROWS, NTH, smem_bytes>>>(
        init_hidden, plan, gatep, init_state, bd1, Wd2, bd2, out);
}

// round 8
// speedup vs baseline: 1.0763x; 1.0763x over previous
#include <cuda_runtime.h>
#include <cstdint>

// Problem constants
#define BATCH   32768
#define TSTEPS  30
#define HID     384
#define KTOT    392     // 8 rowvec + 384 hidden
#define NKB     49      // K blocks of 8
#define NMAIN   144     // fragments per kb in main B (24 ub * 6)
#define MROWS   32      // batch rows per CTA
#define NTH     256     // 8 warps
#define LDH     396     // sA row stride (392 + 4)
#define ASZ     (MROWS*LDH)

// -------- static device scratch --------
__device__ float2 g_B2[NKB * NMAIN * 32];   // main GEMM B (r,z,n_h), fragment order
__device__ float2 g_Bni[48 * 32];           // n_i B: kb=0 only, 24 ub * 2 uh
__device__ float2 g_Wd1f2[48 * 8 * 32];     // decode B, fragment order

__device__ __forceinline__ float to_tf32(float x) {
    unsigned u; asm("cvt.rna.tf32.f32 %0, %1;" : "=r"(u) : "f"(x));
    return __uint_as_float(u);
}
__device__ __forceinline__ float sigf(float x) { return 1.0f / (1.0f + __expf(-x)); }
__device__ __forceinline__ float tanhf_fast(float x) {
    return 2.0f / (1.0f + __expf(-2.0f * x)) - 1.0f;
}

__device__ __forceinline__ void mma_tf32r(float* c, const unsigned* a, unsigned b0, unsigned b1) {
    asm volatile(
        "mma.sync.aligned.m16n8k8.row.col.f32.tf32.tf32.f32 "
        "{%0,%1,%2,%3}, {%4,%5,%6,%7}, {%8,%9}, {%0,%1,%2,%3};\n"
        : "+f"(c[0]), "+f"(c[1]), "+f"(c[2]), "+f"(c[3])
        : "r"(a[0]), "r"(a[1]), "r"(a[2]), "r"(a[3]), "r"(b0), "r"(b1));
}

// -------- prep helpers (layouts identical to rounds 3-7) --------
__device__ float bval_main(int k, int ub, int colub,
                           const float* Wih, const float* bih,
                           const float* Whh, const float* bhh,
                           const float* Wp, const float* bp,
                           const float* Ws, const float* bs) {
    int gate = colub >> 4;          // 0=r,1=z,2=n_h
    int u = ub * 16 + (colub & 15);
    if (k >= 8) {
        int kk = k - 8;
        int grow = (gate == 2 ? 768 : gate * 384) + u;
        return Whh[grow * HID + kk];
    }
    if (gate == 2) return (k == 0) ? bhh[768 + u] : 0.0f;   // n_h: bias only
    int grow = gate * 384 + u;
    const float* wr = Wih + grow * 128;
    float s = 0.0f;
    if (k == 0) {
        s = bih[grow] + bhh[grow];
        for (int m = 0; m < 128; m++) s += bs[m] * wr[m];
    } else if (k == 1) {
        for (int m = 0; m < 128; m++) s += bp[m] * wr[m];
    } else if (k < 5) {
        int d = k - 2;
        for (int m = 0; m < 128; m++) s += Ws[m * 3 + d] * wr[m];
    } else {
        int d = k - 5;
        for (int m = 0; m < 128; m++) s += Wp[m * 3 + d] * wr[m];
    }
    return s;
}

__device__ float bval_ni(int k, int u,
                         const float* Wih, const float* bih,
                         const float* Wp, const float* bp,
                         const float* Ws, const float* bs) {
    int grow = 768 + u;
    const float* wr = Wih + grow * 128;
    float s = 0.0f;
    if (k == 0) {
        s = bih[grow];
        for (int m = 0; m < 128; m++) s += bs[m] * wr[m];
    } else if (k == 1) {
        for (int m = 0; m < 128; m++) s += bp[m] * wr[m];
    } else if (k < 5) {
        int d = k - 2;
        for (int m = 0; m < 128; m++) s += Ws[m * 3 + d] * wr[m];
    } else {
        int d = k - 5;
        for (int m = 0; m < 128; m++) s += Wp[m * 3 + d] * wr[m];
    }
    return s;
}

__global__ void prep_kernel(const float* __restrict__ W_ih, const float* __restrict__ b_ih,
                            const float* __restrict__ W_hh, const float* __restrict__ b_hh,
                            const float* __restrict__ Wp,  const float* __restrict__ bp,
                            const float* __restrict__ Ws,  const float* __restrict__ bs,
                            const float* __restrict__ Wd1) {
    int gid = blockIdx.x * blockDim.x + threadIdx.x;
    int nMain = NKB * NMAIN;
    int total = (nMain + 48 + 48 * 8) * 32;
    for (int w = gid; w < total; w += gridDim.x * blockDim.x) {
        int fid = w >> 5, lane = w & 31;
        int tig = lane & 3, g = lane >> 2;
        if (fid < nMain) {
            int kb = fid / NMAIN, rem = fid - kb * NMAIN;
            int ub = rem / 6, n8l = rem - ub * 6;
            int colub = n8l * 8 + g;
            float b0 = bval_main(kb * 8 + tig,     ub, colub, W_ih, b_ih, W_hh, b_hh, Wp, bp, Ws, bs);
            float b1 = bval_main(kb * 8 + tig + 4, ub, colub, W_ih, b_ih, W_hh, b_hh, Wp, bp, Ws, bs);
            g_B2[fid * 32 + lane] = make_float2(to_tf32(b0), to_tf32(b1));
        } else if (fid < nMain + 48) {
            int f = fid - nMain;            // ub*2 + uh
            int ub = f >> 1, n8l = f & 1;
            int u = ub * 16 + n8l * 8 + g;
            float b0 = bval_ni(tig,     u, W_ih, b_ih, Wp, bp, Ws, bs);
            float b1 = bval_ni(tig + 4, u, W_ih, b_ih, Wp, bp, Ws, bs);
            g_Bni[f * 32 + lane] = make_float2(to_tf32(b0), to_tf32(b1));
        } else {
            int f = fid - nMain - 48;       // 48 kb * 8 n8
            int kb = f >> 3, n8 = f & 7;
            int n = n8 * 8 + g;
            int k = kb * 8 + tig;
            float b0 = Wd1[n * HID + k];
            float b1 = Wd1[n * HID + k + 4];
            g_Wd1f2[f * 32 + lane] = make_float2(to_tf32(b0), to_tf32(b1));
        }
    }
}

// -------- main fused GRU rollout: 8 warps x 32-row tile, 2 CTAs/SM --------
__global__ __launch_bounds__(NTH, 2)
void gru_kernel(const float* __restrict__ init_hidden,
                const float* __restrict__ plan,
                const float* __restrict__ gate,
                const float* __restrict__ init_state,
                const float* __restrict__ bd1,
                const float* __restrict__ Wd2,
                const float* __restrict__ bd2,
                float* __restrict__ out) {
    extern __shared__ float sm[];
    float* sA0   = sm;                  // [MROWS][LDH] ping
    float* sA1   = sA0 + ASZ;           // pong
    float* sDec  = sA1 + ASZ;           // [32][68]
    float* sStat = sDec + 32 * 68;      // [32*3]
    float* sGate = sStat + 96;          // [32]
    float* sbd1  = sGate + 32;          // [64]
    float* sWd2  = sbd1 + 64;           // [3*64]
    float* sbd2  = sWd2 + 192;          // [4]

    const int tid  = threadIdx.x;
    const int warp = tid >> 5;
    const int lane = tid & 31;
    const int g8   = lane >> 2;
    const int tig  = lane & 3;
    const int row0 = blockIdx.x * MROWS;

    for (int i = tid; i < MROWS * HID; i += NTH) {
        int r = i / HID, u = i - r * HID;
        sA0[r * LDH + 8 + u] = to_tf32(init_hidden[(size_t)row0 * HID + i]);
    }
    if (tid < 96)  sStat[tid] = init_state[(size_t)row0 * 3 + tid];
    if (tid < 192) sWd2[tid] = Wd2[tid];
    if (tid < 32)  sGate[tid] = gate[row0 + tid];
    if (tid < 64)  sbd1[tid] = bd1[tid];
    if (tid < 3)   sbd2[tid] = bd2[tid];
    __syncthreads();

    for (int t = 0; t < TSTEPS; t++) {
        float* Acur = (t & 1) ? sA1 : sA0;
        float* Anxt = (t & 1) ? sA0 : sA1;

        // ---- phase 0: rowvec = [1, g, S, g*P] into cols 0..7 (256 lanes = 32x8) ----
        {
            int r = tid >> 3, c = tid & 7;
            float v;
            if (c == 0)      v = 1.0f;
            else if (c == 1) v = sGate[r];
            else if (c < 5)  v = sStat[r * 3 + (c - 2)];
            else             v = sGate[r] * plan[((size_t)(row0 + r) * TSTEPS + t) * 3 + (c - 5)];
            Acur[r * LDH + c] = to_tf32(v);
        }
        __syncthreads();

        // ---- phase 1: GEMM (32 x 1152 dense + n_i micro) + gate math ----
        for (int task = 0; task < 3; task++) {
            const int ub = warp + 8 * task;     // u-block 0..23 (16 cols)

            float acc[48];                      // [mf=2][6 frags] x 4  (r,z,n_h)
            float accN[16];                     // [mf=2][uh] x 4       (n_i)
            #pragma unroll
            for (int i = 0; i < 48; i++) acc[i] = 0.0f;
            #pragma unroll
            for (int i = 0; i < 16; i++) accN[i] = 0.0f;

            const float2* Bbase = g_B2 + (size_t)(ub * 6) * 32 + lane;
            float2 bb[2][6];
            #pragma unroll
            for (int j = 0; j < 6; j++) bb[0][j] = Bbase[j * 32];
            float2 bni0 = g_Bni[(ub * 2 + 0) * 32 + lane];
            float2 bni1 = g_Bni[(ub * 2 + 1) * 32 + lane];

            #pragma unroll 2
            for (int kb = 0; kb < NKB; kb++) {
                const int cur = kb & 1;
                if (kb < NKB - 1) {
                    const float2* Bn = Bbase + (size_t)(kb + 1) * (NMAIN * 32);
                    #pragma unroll
                    for (int j = 0; j < 6; j++) bb[cur ^ 1][j] = Bn[j * 32];
                }
                unsigned a[8];
                const float* Ab = Acur + kb * 8;
                #pragma unroll
                for (int mf = 0; mf < 2; mf++) {
                    int r0 = mf * 16 + g8;
                    a[mf * 4 + 0] = __float_as_uint(Ab[r0 * LDH + tig]);
                    a[mf * 4 + 1] = __float_as_uint(Ab[(r0 + 8) * LDH + tig]);
                    a[mf * 4 + 2] = __float_as_uint(Ab[r0 * LDH + tig + 4]);
                    a[mf * 4 + 3] = __float_as_uint(Ab[(r0 + 8) * LDH + tig + 4]);
                }
                if (kb == 0) {   // n_i: rowvec-only contribution
                    unsigned n0x = __float_as_uint(bni0.x), n0y = __float_as_uint(bni0.y);
                    unsigned n1x = __float_as_uint(bni1.x), n1y = __float_as_uint(bni1.y);
                    #pragma unroll
                    for (int mf = 0; mf < 2; mf++) {
                        mma_tf32r(&accN[(mf * 2 + 0) * 4], &a[mf * 4], n0x, n0y);
                        mma_tf32r(&accN[(mf * 2 + 1) * 4], &a[mf * 4], n1x, n1y);
                    }
                }
                #pragma unroll
                for (int f = 0; f < 6; f++) {
                    unsigned b0 = __float_as_uint(bb[cur][f].x);
                    unsigned b1 = __float_as_uint(bb[cur][f].y);
                    #pragma unroll
                    for (int mf = 0; mf < 2; mf++)
                        mma_tf32r(&acc[(mf * 6 + f) * 4], &a[mf * 4], b0, b1);
                }
            }

            // gate math on fragments (f = gate*2 + uh)
            #pragma unroll
            for (int mf = 0; mf < 2; mf++)
            #pragma unroll
            for (int uh = 0; uh < 2; uh++)
            #pragma unroll
            for (int e = 0; e < 4; e++) {
                int row = mf * 16 + g8 + ((e >> 1) << 3);
                int u   = ub * 16 + uh * 8 + tig * 2 + (e & 1);
                float aR  = acc[(mf * 6 + 0 + uh) * 4 + e];
                float aZ  = acc[(mf * 6 + 2 + uh) * 4 + e];
                float aNh = acc[(mf * 6 + 4 + uh) * 4 + e];
                float aNi = accN[(mf * 2 + uh) * 4 + e];
                float rg = sigf(aR);
                float zg = sigf(aZ);
                float n  = tanhf_fast(aNi + rg * aNh);
                float hold = Acur[row * LDH + 8 + u];
                float hnew = (1.0f - zg) * n + zg * hold;
                Anxt[row * LDH + 8 + u] = to_tf32(hnew);
            }
        }
        __syncthreads();

        // ---- phase 2: decode layer1 (32x64, K=384) ----
        {
            float dacc[8];
            #pragma unroll
            for (int i = 0; i < 8; i++) dacc[i] = 0.0f;

            float2 bv = g_Wd1f2[warp * 32 + lane];
            #pragma unroll 2
            for (int kb = 0; kb < 48; kb++) {
                float2 bcur = bv;
                if (kb < 47) bv = g_Wd1f2[((kb + 1) * 8 + warp) * 32 + lane];
                unsigned a[8];
                const float* Ab = Anxt + 8 + kb * 8;
                #pragma unroll
                for (int mf = 0; mf < 2; mf++) {
                    int r0 = mf * 16 + g8;
                    a[mf * 4 + 0] = __float_as_uint(Ab[r0 * LDH + tig]);
                    a[mf * 4 + 1] = __float_as_uint(Ab[(r0 + 8) * LDH + tig]);
                    a[mf * 4 + 2] = __float_as_uint(Ab[r0 * LDH + tig + 4]);
                    a[mf * 4 + 3] = __float_as_uint(Ab[(r0 + 8) * LDH + tig + 4]);
                }
                unsigned b0 = __float_as_uint(bcur.x), b1 = __float_as_uint(bcur.y);
                #pragma unroll
                for (int mf = 0; mf < 2; mf++)
                    mma_tf32r(&dacc[mf * 4], &a[mf * 4], b0, b1);
            }
            #pragma unroll
            for (int mf = 0; mf < 2; mf++)
            #pragma unroll
            for (int e = 0; e < 4; e++) {
                int row = mf * 16 + g8 + ((e >> 1) << 3);
                int col = warp * 8 + tig * 2 + (e & 1);
                float v = dacc[mf * 4 + e] + sbd1[col];
                v = v > 0.0f ? v : (__expf(v) - 1.0f);   // ELU
                sDec[row * 68 + col] = v;
            }
        }
        __syncthreads();

        // ---- phase 3: decode layer2 + state update + output ----
        if (tid < 96) {
            int r = tid / 3, c = tid - r * 3;
            float acc = sbd2[c];
            const float* w2 = sWd2 + c * 64;
            const float* dp = sDec + r * 68;
            #pragma unroll 16
            for (int k = 0; k < 64; k++) acc += dp[k] * w2[k];
            float ns = sStat[tid] + acc;
            sStat[tid] = ns;
            out[((size_t)(row0 + r) * TSTEPS + t) * 3 + c] = ns;
        }
        __syncthreads();
    }
}

// -------- launch --------
extern "C" void kernel_launch(void* const* d_in, const int* in_sizes, int n_in,
                              void* d_out, int out_size) {
    const float* init_hidden = (const float*)d_in[0];
    const float* plan        = (const float*)d_in[1];
    const float* gatep       = (const float*)d_in[2];
    const float* init_state  = (const float*)d_in[3];
    const float* Wp   = (const float*)d_in[4];
    const float* bp   = (const float*)d_in[5];
    const float* Ws   = (const float*)d_in[6];
    const float* bs   = (const float*)d_in[7];
    const float* W_ih = (const float*)d_in[8];
    const float* b_ih = (const float*)d_in[9];
    const float* W_hh = (const float*)d_in[10];
    const float* b_hh = (const float*)d_in[11];
    const float* Wd1  = (const float*)d_in[12];
    const float* bd1  = (const float*)d_in[13];
    const float* Wd2  = (const float*)d_in[14];
    const float* bd2  = (const float*)d_in[15];
    float* out = (float*)d_out;

    prep_kernel<<<640, 256>>>(W_ih, b_ih, W_hh, b_hh, Wp, bp, Ws, bs, Wd1);

    const size_t smem_floats = 2 * (size_t)ASZ + 32 * 68 + 96 + 32 + 64 + 192 + 4;
    const size_t smem_bytes = smem_floats * sizeof(float);
    cudaFuncSetAttribute(gru_kernel, cudaFuncAttributeMaxDynamicSharedMemorySize,
                         (int)smem_bytes);

    gru_kernel<<<BATCH / MROWS, NTH, smem_bytes>>>(
        init_hidden, plan, gatep, init_state, bd1, Wd2, bd2, out);
}

// round 9
// speedup vs baseline: 2.2106x; 2.0539x over previous
#include <cuda_runtime.h>
#include <cuda_fp16.h>
#include <cstdint>

// Problem constants
#define BATCH   32768
#define TSTEPS  30
#define HID     384
#define KTOT    400     // 8 rowvec + 384 hidden + 8 zero pad
#define NKB     25      // K blocks of 16
#define NMAIN   144     // fragments per kb (24 ub * 6: gate3 x uh2)
#define MROWS   64      // batch rows per CTA
#define NTH     256     // 8 warps; 2 CTAs/SM
#define LDHH    408     // sA row stride in halfs (word stride 204 -> LDS conflict-free)
#define WLDH    204     // row stride in 32-bit words
#define AHSZ    (MROWS*LDHH)   // halfs per A buffer
#define DECLD   66      // sDec row stride in halfs (even -> half2 aligned)

// -------- static device scratch (fp16 fragment tables) --------
__device__ uint2 g_Bh[NKB * NMAIN * 32];    // main GEMM B (r,z,n_h)
__device__ uint2 g_Bnih[48 * 32];           // n_i B: kb=0 only, 48 usb
__device__ uint2 g_Wd1h[24 * 8 * 32];       // decode B

__device__ __forceinline__ unsigned packh2(float a, float b) {
    __half2 h = __floats2half2_rn(a, b);    // .x = a (low half / even col)
    return *reinterpret_cast<unsigned*>(&h);
}
__device__ __forceinline__ float sigf(float x) { return 1.0f / (1.0f + __expf(-x)); }
__device__ __forceinline__ float tanhf_fast(float x) {
    return 2.0f / (1.0f + __expf(-2.0f * x)) - 1.0f;
}

__device__ __forceinline__ void mma_f16(float* c, const unsigned* a, unsigned b0, unsigned b1) {
    asm volatile(
        "mma.sync.aligned.m16n8k16.row.col.f32.f16.f16.f32 "
        "{%0,%1,%2,%3}, {%4,%5,%6,%7}, {%8,%9}, {%0,%1,%2,%3};\n"
        : "+f"(c[0]), "+f"(c[1]), "+f"(c[2]), "+f"(c[3])
        : "r"(a[0]), "r"(a[1]), "r"(a[2]), "r"(a[3]), "r"(b0), "r"(b1));
}

// -------- prep value helpers (same math as rounds 3-8, with K pad guard) --------
__device__ float bval_main(int k, int ub, int colub,
                           const float* Wih, const float* bih,
                           const float* Whh, const float* bhh,
                           const float* Wp, const float* bp,
                           const float* Ws, const float* bs) {
    if (k >= 392) return 0.0f;               // K pad
    int gate = colub >> 4;                   // 0=r,1=z,2=n_h
    int u = ub * 16 + (colub & 15);
    if (k >= 8) {
        int kk = k - 8;
        int grow = (gate == 2 ? 768 : gate * 384) + u;
        return Whh[grow * HID + kk];
    }
    if (gate == 2) return (k == 0) ? bhh[768 + u] : 0.0f;   // n_h: bias only
    int grow = gate * 384 + u;
    const float* wr = Wih + grow * 128;
    float s = 0.0f;
    if (k == 0) {
        s = bih[grow] + bhh[grow];
        for (int m = 0; m < 128; m++) s += bs[m] * wr[m];
    } else if (k == 1) {
        for (int m = 0; m < 128; m++) s += bp[m] * wr[m];
    } else if (k < 5) {
        int d = k - 2;
        for (int m = 0; m < 128; m++) s += Ws[m * 3 + d] * wr[m];
    } else {
        int d = k - 5;
        for (int m = 0; m < 128; m++) s += Wp[m * 3 + d] * wr[m];
    }
    return s;
}

__device__ float bval_ni(int k, int u,
                         const float* Wih, const float* bih,
                         const float* Wp, const float* bp,
                         const float* Ws, const float* bs) {
    if (k >= 8) return 0.0f;                 // n_i: rowvec only
    int grow = 768 + u;
    const float* wr = Wih + grow * 128;
    float s = 0.0f;
    if (k == 0) {
        s = bih[grow];
        for (int m = 0; m < 128; m++) s += bs[m] * wr[m];
    } else if (k == 1) {
        for (int m = 0; m < 128; m++) s += bp[m] * wr[m];
    } else if (k < 5) {
        int d = k - 2;
        for (int m = 0; m < 128; m++) s += Ws[m * 3 + d] * wr[m];
    } else {
        int d = k - 5;
        for (int m = 0; m < 128; m++) s += Wp[m * 3 + d] * wr[m];
    }
    return s;
}

__global__ void prep_kernel(const float* __restrict__ W_ih, const float* __restrict__ b_ih,
                            const float* __restrict__ W_hh, const float* __restrict__ b_hh,
                            const float* __restrict__ Wp,  const float* __restrict__ bp,
                            const float* __restrict__ Ws,  const float* __restrict__ bs,
                            const float* __restrict__ Wd1) {
    int gid = blockIdx.x * blockDim.x + threadIdx.x;
    const int nMain = NKB * NMAIN;
    const int total = (nMain + 48 + 24 * 8) * 32;
    for (int w = gid; w < total; w += gridDim.x * blockDim.x) {
        int fid = w >> 5, lane = w & 31;
        int tig = lane & 3, g = lane >> 2;
        if (fid < nMain) {
            int kb = fid / NMAIN, rem = fid - kb * NMAIN;
            int ub = rem / 6, n8l = rem - ub * 6;
            int colub = n8l * 8 + g;
            int k0 = kb * 16;
            float v00 = bval_main(k0 + 2 * tig,     ub, colub, W_ih, b_ih, W_hh, b_hh, Wp, bp, Ws, bs);
            float v01 = bval_main(k0 + 2 * tig + 1, ub, colub, W_ih, b_ih, W_hh, b_hh, Wp, bp, Ws, bs);
            float v10 = bval_main(k0 + 2 * tig + 8, ub, colub, W_ih, b_ih, W_hh, b_hh, Wp, bp, Ws, bs);
            float v11 = bval_main(k0 + 2 * tig + 9, ub, colub, W_ih, b_ih, W_hh, b_hh, Wp, bp, Ws, bs);
            g_Bh[fid * 32 + lane] = make_uint2(packh2(v00, v01), packh2(v10, v11));
        } else if (fid < nMain + 48) {
            int usb = fid - nMain;
            int u = usb * 8 + g;
            float v00 = bval_ni(2 * tig,     u, W_ih, b_ih, Wp, bp, Ws, bs);
            float v01 = bval_ni(2 * tig + 1, u, W_ih, b_ih, Wp, bp, Ws, bs);
            g_Bnih[usb * 32 + lane] = make_uint2(packh2(v00, v01), packh2(0.0f, 0.0f));
        } else {
            int f = fid - nMain - 48;        // 24 kd * 8 c8
            int kd = f >> 3, c8 = f & 7;
            int n = c8 * 8 + g;
            int k = kd * 16 + 2 * tig;
            float v00 = Wd1[n * HID + k];
            float v01 = Wd1[n * HID + k + 1];
            float v10 = Wd1[n * HID + k + 8];
            float v11 = Wd1[n * HID + k + 9];
            g_Wd1h[f * 32 + lane] = make_uint2(packh2(v00, v01), packh2(v10, v11));
        }
    }
}

// -------- main fused GRU rollout: fp16 MMA, 8 warps, 2 CTAs/SM --------
__global__ __launch_bounds__(NTH, 2)
void gru_kernel(const float* __restrict__ init_hidden,
                const float* __restrict__ plan,
                const float* __restrict__ gate,
                const float* __restrict__ init_state,
                const float* __restrict__ bd1,
                const float* __restrict__ Wd2,
                const float* __restrict__ bd2,
                float* __restrict__ out) {
    extern __shared__ char smraw[];
    __half* sA0h  = (__half*)smraw;                 // [64][408] ping
    __half* sA1h  = sA0h + AHSZ;                    // pong
    __half* sDech = sA1h + AHSZ;                    // [64][66]
    float*  sStat = (float*)(sDech + 64 * DECLD);   // [192]
    float*  sGate = sStat + 192;                    // [64]
    float*  sbd1  = sGate + 64;                     // [64]
    float*  sWd2  = sbd1 + 64;                      // [192]
    float*  sbd2  = sWd2 + 192;                     // [4]

    const int tid  = threadIdx.x;
    const int warp = tid >> 5;
    const int lane = tid & 31;
    const int g8   = lane >> 2;
    const int tig  = lane & 3;
    const int row0 = blockIdx.x * MROWS;

    // ---- init ----
    for (int i = tid; i < MROWS * HID; i += NTH) {
        int r = i / HID, u = i - r * HID;
        sA0h[r * LDHH + 8 + u] = __float2half_rn(init_hidden[(size_t)row0 * HID + i]);
    }
    for (int i = tid; i < MROWS * 8; i += NTH) {   // zero K-pad cols 392..399, both buffers
        int r = i >> 3, c = i & 7;
        sA0h[r * LDHH + 392 + c] = __ushort_as_half(0);
        sA1h[r * LDHH + 392 + c] = __ushort_as_half(0);
    }
    if (tid < 192) { sStat[tid] = init_state[(size_t)row0 * 3 + tid]; sWd2[tid] = Wd2[tid]; }
    if (tid < 64)  { sGate[tid] = gate[row0 + tid]; sbd1[tid] = bd1[tid]; }
    if (tid < 3)   sbd2[tid] = bd2[tid];
    __syncthreads();

    for (int t = 0; t < TSTEPS; t++) {
        __half* Acur = (t & 1) ? sA1h : sA0h;
        __half* Anxt = (t & 1) ? sA0h : sA1h;
        const unsigned* Aw = (const unsigned*)Acur;

        // ---- phase 0: rowvec = [1, g, S0..2, g*P0..2] into cols 0..7 (half2 pairs) ----
        {
            int r = tid >> 2, c2 = tid & 3;        // 64 rows x 4 half2 words
            float g0 = sGate[r];
            float v0, v1;
            if (c2 == 0)      { v0 = 1.0f;          v1 = g0; }
            else if (c2 == 1) { v0 = sStat[r * 3];  v1 = sStat[r * 3 + 1]; }
            else if (c2 == 2) { v0 = sStat[r * 3 + 2];
                                v1 = g0 * plan[((size_t)(row0 + r) * TSTEPS + t) * 3 + 0]; }
            else              { v0 = g0 * plan[((size_t)(row0 + r) * TSTEPS + t) * 3 + 1];
                                v1 = g0 * plan[((size_t)(row0 + r) * TSTEPS + t) * 3 + 2]; }
            ((unsigned*)Acur)[r * WLDH + c2] = packh2(v0, v1);
        }
        __syncthreads();

        // ---- phase 1: GEMM (64 x 1152 dense + n_i micro) + gate math ----
        for (int task = 0; task < 6; task++) {
            const int usb = warp + 8 * task;       // 8-col sub-block 0..47
            const int ub  = usb >> 1;
            const int uh  = usb & 1;

            float acc[48];                         // [mf=4][gate=3] x 4
            float accN[16];                        // [mf=4] x 4 (n_i)
            #pragma unroll
            for (int i = 0; i < 48; i++) acc[i] = 0.0f;
            #pragma unroll
            for (int i = 0; i < 16; i++) accN[i] = 0.0f;

            const uint2* Bbase = g_Bh + (size_t)(ub * 6 + uh) * 32 + lane;
            uint2 bb[2][3];
            #pragma unroll
            for (int gi = 0; gi < 3; gi++) bb[0][gi] = Bbase[gi * 64];
            uint2 bni = g_Bnih[usb * 32 + lane];

            #pragma unroll 5
            for (int kb = 0; kb < NKB; kb++) {
                const int cur = kb & 1;
                if (kb < NKB - 1) {
                    const uint2* Bn = Bbase + (size_t)(kb + 1) * (NMAIN * 32);
                    #pragma unroll
                    for (int gi = 0; gi < 3; gi++) bb[cur ^ 1][gi] = Bn[gi * 64];
                }
                // A fragments: 16 LDS.32 of half2, conflict-free
                unsigned a[16];
                #pragma unroll
                for (int mf = 0; mf < 4; mf++) {
                    int r0 = mf * 16 + g8;
                    int wbase = kb * 8 + tig;
                    a[mf * 4 + 0] = Aw[r0 * WLDH + wbase];
                    a[mf * 4 + 1] = Aw[(r0 + 8) * WLDH + wbase];
                    a[mf * 4 + 2] = Aw[r0 * WLDH + wbase + 4];
                    a[mf * 4 + 3] = Aw[(r0 + 8) * WLDH + wbase + 4];
                }
                if (kb == 0) {   // n_i: rowvec-only contribution
                    #pragma unroll
                    for (int mf = 0; mf < 4; mf++)
                        mma_f16(&accN[mf * 4], &a[mf * 4], bni.x, bni.y);
                }
                #pragma unroll
                for (int gi = 0; gi < 3; gi++) {
                    #pragma unroll
                    for (int mf = 0; mf < 4; mf++)
                        mma_f16(&acc[(mf * 3 + gi) * 4], &a[mf * 4], bb[cur][gi].x, bb[cur][gi].y);
                }
            }

            // gate math on fragments; write hidden as half2 pairs
            #pragma unroll
            for (int mf = 0; mf < 4; mf++)
            #pragma unroll
            for (int h = 0; h < 2; h++) {
                int row = mf * 16 + g8 + h * 8;
                int widx = row * WLDH + 4 + usb * 4 + tig;   // word of cols 8+usb*8+2tig
                int e0 = 2 * h;                               // c-layout: e0,e1 same row, cols 2t,2t+1
                __half2 hold2 = *(const __half2*)&Aw[widx];
                float2 holdf = __half22float2(hold2);
                float hn[2];
                #pragma unroll
                for (int q = 0; q < 2; q++) {
                    int e = e0 + q;
                    float rg = sigf(acc[(mf * 3 + 0) * 4 + e]);
                    float zg = sigf(acc[(mf * 3 + 1) * 4 + e]);
                    float nn = tanhf_fast(accN[mf * 4 + e] + rg * acc[(mf * 3 + 2) * 4 + e]);
                    float ho = (q == 0) ? holdf.x : holdf.y;
                    hn[q] = (1.0f - zg) * nn + zg * ho;
                }
                ((unsigned*)Anxt)[widx] = packh2(hn[0], hn[1]);
            }
        }
        __syncthreads();

        // ---- phase 2: decode layer1 (64x64, K=384) fp16 MMA ----
        {
            const unsigned* Anw = (const unsigned*)Anxt;
            float dacc[16];
            #pragma unroll
            for (int i = 0; i < 16; i++) dacc[i] = 0.0f;

            uint2 bv = g_Wd1h[warp * 32 + lane];
            #pragma unroll 2
            for (int kd = 0; kd < 24; kd++) {
                uint2 bcur = bv;
                if (kd < 23) bv = g_Wd1h[((kd + 1) * 8 + warp) * 32 + lane];
                unsigned a[16];
                #pragma unroll
                for (int mf = 0; mf < 4; mf++) {
                    int r0 = mf * 16 + g8;
                    int wbase = 4 + kd * 8 + tig;
                    a[mf * 4 + 0] = Anw[r0 * WLDH + wbase];
                    a[mf * 4 + 1] = Anw[(r0 + 8) * WLDH + wbase];
                    a[mf * 4 + 2] = Anw[r0 * WLDH + wbase + 4];
                    a[mf * 4 + 3] = Anw[(r0 + 8) * WLDH + wbase + 4];
                }
                #pragma unroll
                for (int mf = 0; mf < 4; mf++)
                    mma_f16(&dacc[mf * 4], &a[mf * 4], bcur.x, bcur.y);
            }
            #pragma unroll
            for (int mf = 0; mf < 4; mf++)
            #pragma unroll
            for (int h = 0; h < 2; h++) {
                int row = mf * 16 + g8 + h * 8;
                int col = warp * 8 + tig * 2;
                float v0 = dacc[mf * 4 + 2 * h]     + sbd1[col];
                float v1 = dacc[mf * 4 + 2 * h + 1] + sbd1[col + 1];
                v0 = v0 > 0.0f ? v0 : (__expf(v0) - 1.0f);    // ELU
                v1 = v1 > 0.0f ? v1 : (__expf(v1) - 1.0f);
                *(unsigned*)(sDech + row * DECLD + col) = packh2(v0, v1);
            }
        }
        __syncthreads();

        // ---- phase 3: decode layer2 + state update + output ----
        if (tid < 192) {
            int r = tid / 3, c = tid - r * 3;
            float acc = sbd2[c];
            const float* w2 = sWd2 + c * 64;
            const __half2* dp = (const __half2*)(sDech + r * DECLD);
            #pragma unroll 8
            for (int k2 = 0; k2 < 32; k2++) {
                float2 f = __half22float2(dp[k2]);
                acc += f.x * w2[2 * k2] + f.y * w2[2 * k2 + 1];
            }
            float ns = sStat[tid] + acc;
            sStat[tid] = ns;
            out[((size_t)(row0 + r) * TSTEPS + t) * 3 + c] = ns;
        }
        __syncthreads();
    }
}

// -------- launch --------
extern "C" void kernel_launch(void* const* d_in, const int* in_sizes, int n_in,
                              void* d_out, int out_size) {
    const float* init_hidden = (const float*)d_in[0];
    const float* plan        = (const float*)d_in[1];
    const float* gatep       = (const float*)d_in[2];
    const float* init_state  = (const float*)d_in[3];
    const float* Wp   = (const float*)d_in[4];
    const float* bp   = (const float*)d_in[5];
    const float* Ws   = (const float*)d_in[6];
    const float* bs   = (const float*)d_in[7];
    const float* W_ih = (const float*)d_in[8];
    const float* b_ih = (const float*)d_in[9];
    const float* W_hh = (const float*)d_in[10];
    const float* b_hh = (const float*)d_in[11];
    const float* Wd1  = (const float*)d_in[12];
    const float* bd1  = (const float*)d_in[13];
    const float* Wd2  = (const float*)d_in[14];
    const float* bd2  = (const float*)d_in[15];
    float* out = (float*)d_out;

    prep_kernel<<<480, 256>>>(W_ih, b_ih, W_hh, b_hh, Wp, bp, Ws, bs, Wd1);

    const size_t smem_bytes = (size_t)(2 * AHSZ + 64 * DECLD) * sizeof(__half)
                            + (192 + 64 + 64 + 192 + 4) * sizeof(float);
    cudaFuncSetAttribute(gru_kernel, cudaFuncAttributeMaxDynamicSharedMemorySize,
                         (int)smem_bytes);

    gru_kernel<<<BATCH / MROWS, NTH, smem_bytes>>>(
        init_hidden, plan, gatep, init_state, bd1, Wd2, bd2, out);
}